// round 1
// baseline (speedup 1.0000x reference)
#include <cuda_runtime.h>
#include <cstdint>
#include <cstddef>

// Reservoir: x_{t+1} = tanh(W x_t + w_in * u_t), leak=1.0
// B=8192 chains, T=4096 steps, hidden=16.
// Layout: 2 lanes per chain; lane h owns outputs [8h, 8h+8) as 4 fp32x2 pairs.
// W held in registers as fp32x2 pairs (Blackwell has no cbank ALU operands).
// Lane-local column remap (gj = (8h+j)&15) so xd[0..7] is always "own" outputs
// and xd[8..15] is always "partner" outputs -> uniform register indexing.

#define HID 16
#define TT  4096
#define BB  8192

typedef unsigned long long u64;

__device__ __forceinline__ u64 pack2(float a, float b) {
    u64 r; asm("mov.b64 %0, {%1, %2};" : "=l"(r) : "f"(a), "f"(b)); return r;
}
__device__ __forceinline__ u64 dup1(float a) { return pack2(a, a); }
__device__ __forceinline__ void unpack2(u64 v, float& a, float& b) {
    asm("mov.b64 {%0, %1}, %2;" : "=f"(a), "=f"(b) : "l"(v));
}
__device__ __forceinline__ void fma2(u64& d, u64 a, u64 b) {
    asm("fma.rn.f32x2 %0, %1, %2, %0;" : "+l"(d) : "l"(a), "l"(b));
}
__device__ __forceinline__ u64 mul2(u64 a, u64 b) {
    u64 d; asm("mul.rn.f32x2 %0, %1, %2;" : "=l"(d) : "l"(a), "l"(b)); return d;
}

// Fast accurate-enough tanh: t = 1 - 2/(exp2(2*log2e*x)+1).
// ex2.approx / rcp.approx rel err ~2^-22 -> per-step error ~1e-6, contracts at rho=0.9.
// Overflow-safe: x>>0 -> ex=inf -> rcp=0 -> t=1; x<<0 -> ex=0 -> t=-1.
__device__ __forceinline__ float ftanh(float x) {
    float xs = x * 2.8853900817779268f;  // 2*log2(e)
    float ex; asm("ex2.approx.f32 %0, %1;" : "=f"(ex) : "f"(xs));
    float den = ex + 1.0f;
    float r;  asm("rcp.approx.f32 %0, %1;" : "=f"(r) : "f"(den));
    return fmaf(-2.0f, r, 1.0f);
}

__global__ __launch_bounds__(128, 1)
void reservoir_kernel(const float* __restrict__ rain,
                      const float* __restrict__ w_in,
                      const float* __restrict__ w,
                      float* __restrict__ out)
{
    const int tid   = blockIdx.x * 128 + threadIdx.x;
    const int b     = tid >> 1;      // chain (batch element)
    const int h     = tid & 1;       // which half of hidden this lane owns
    const int rbase = 8 * h;         // first owned output row

    // --- load W / w_in into registers as fp32x2 pairs over output rows ---
    u64 wp[16][4];   // wp[j][p] = ( W[rbase+2p][gj], W[rbase+2p+1][gj] ), gj=(rbase+j)&15
    u64 winp[4];
#pragma unroll
    for (int p = 0; p < 4; ++p) {
        const int r0 = rbase + 2 * p, r1 = r0 + 1;
        winp[p] = pack2(w_in[r0], w_in[r1]);
#pragma unroll
        for (int j = 0; j < 16; ++j) {
            const int gj = (rbase + j) & 15;
            wp[j][p] = pack2(w[r0 * HID + gj], w[r1 * HID + gj]);
        }
    }

    // state, duplicated into both halves of fp32x2: xd[j] = (x[gj], x[gj])
    u64 xd[16];
#pragma unroll
    for (int j = 0; j < 16; ++j) xd[j] = 0ull;

    const float4* up = reinterpret_cast<const float4*>(rain + (size_t)b * TT);

    float4 ua = up[0], ub = up[1];   // current 8 inputs
    float t0, t1, t2, t3, t4, t5, t6, t7;

    const int NG = TT / 8;           // 512 groups of 8 steps

#define STEP(UVAL)                                                            \
    do {                                                                      \
        u64 du = dup1(UVAL);                                                  \
        u64 a0 = mul2(winp[0], du);                                           \
        u64 a1 = mul2(winp[1], du);                                           \
        u64 a2 = mul2(winp[2], du);                                           \
        u64 a3 = mul2(winp[3], du);                                           \
        _Pragma("unroll")                                                     \
        for (int j = 0; j < 16; ++j) {                                        \
            fma2(a0, wp[j][0], xd[j]);                                        \
            fma2(a1, wp[j][1], xd[j]);                                        \
            fma2(a2, wp[j][2], xd[j]);                                        \
            fma2(a3, wp[j][3], xd[j]);                                        \
        }                                                                     \
        float q0, q1;                                                         \
        unpack2(a0, q0, q1); t0 = ftanh(q0); t1 = ftanh(q1);                  \
        unpack2(a1, q0, q1); t2 = ftanh(q0); t3 = ftanh(q1);                  \
        unpack2(a2, q0, q1); t4 = ftanh(q0); t5 = ftanh(q1);                  \
        unpack2(a3, q0, q1); t6 = ftanh(q0); t7 = ftanh(q1);                  \
        float o0 = __shfl_xor_sync(0xFFFFFFFFu, t0, 1);                       \
        float o1 = __shfl_xor_sync(0xFFFFFFFFu, t1, 1);                       \
        float o2 = __shfl_xor_sync(0xFFFFFFFFu, t2, 1);                       \
        float o3 = __shfl_xor_sync(0xFFFFFFFFu, t3, 1);                       \
        float o4 = __shfl_xor_sync(0xFFFFFFFFu, t4, 1);                       \
        float o5 = __shfl_xor_sync(0xFFFFFFFFu, t5, 1);                       \
        float o6 = __shfl_xor_sync(0xFFFFFFFFu, t6, 1);                       \
        float o7 = __shfl_xor_sync(0xFFFFFFFFu, t7, 1);                       \
        xd[0]  = dup1(t0); xd[1]  = dup1(t1); xd[2]  = dup1(t2);              \
        xd[3]  = dup1(t3); xd[4]  = dup1(t4); xd[5]  = dup1(t5);              \
        xd[6]  = dup1(t6); xd[7]  = dup1(t7);                                 \
        xd[8]  = dup1(o0); xd[9]  = dup1(o1); xd[10] = dup1(o2);              \
        xd[11] = dup1(o3); xd[12] = dup1(o4); xd[13] = dup1(o5);              \
        xd[14] = dup1(o6); xd[15] = dup1(o7);                                 \
    } while (0)

    for (int g = 0; g < NG; ++g) {
        const int pg = (g + 1 < NG) ? (g + 1) : g;   // clamp: last iter reloads
        const float4 na = up[2 * pg];                 // prefetch next 8 inputs
        const float4 nb = up[2 * pg + 1];

        STEP(ua.x); STEP(ua.y); STEP(ua.z); STEP(ua.w);
        STEP(ub.x); STEP(ub.y); STEP(ub.z); STEP(ub.w);

        ua = na; ub = nb;
    }
#undef STEP

    // final state: out[b*16 + rbase + k] = t_k  (8 floats, 16B-aligned)
    float* ob = out + (size_t)b * HID + rbase;
    reinterpret_cast<float4*>(ob)[0] = make_float4(t0, t1, t2, t3);
    reinterpret_cast<float4*>(ob)[1] = make_float4(t4, t5, t6, t7);
}

extern "C" void kernel_launch(void* const* d_in, const int* in_sizes, int n_in,
                              void* d_out, int out_size)
{
    const float* rain = (const float*)d_in[0];   // (B, T, 1) f32
    const float* w_in = (const float*)d_in[1];   // (16, 1)   f32
    const float* w    = (const float*)d_in[2];   // (16, 16)  f32
    float* out        = (float*)d_out;           // (B, 16)   f32

    reservoir_kernel<<<(BB * 2) / 128, 128>>>(rain, w_in, w, out);
}

// round 2
// speedup vs baseline: 1.1466x; 1.1466x over previous
#include <cuda_runtime.h>
#include <cstdint>
#include <cstddef>

// Reservoir: x_{t+1} = tanh(W x_t + w_in u_t), B=8192, T=4096, hidden=16.
//
// Layout: 4 lanes per chain; lane h owns rows [4h, 4h+4).
// XOR local map: slot j holds x[(4h) ^ j]  (uniform shfl landing slots).
// State is r = 1/(exp2(c*pre)+1) with c=2*log2(e); x = 1 - 2r folded into
// W'' = -2c*W and per-row bias = c*rowsum(W) + c*w_in*u.
// f32x2 pairs run over INPUT columns (adjacent slots), so state pairs are
// built from adjacent scalars (packs) -- no per-element broadcast MOVs.

#define HID 16
#define TT  4096
#define BB  8192

typedef unsigned long long u64;

__device__ __forceinline__ u64 pack2(float a, float b) {
    u64 r; asm("mov.b64 %0, {%1, %2};" : "=l"(r) : "f"(a), "f"(b)); return r;
}
__device__ __forceinline__ void unpack2(u64 v, float& a, float& b) {
    asm("mov.b64 {%0, %1}, %2;" : "=f"(a), "=f"(b) : "l"(v));
}
__device__ __forceinline__ void fma2(u64& d, u64 a, u64 b) {
    asm("fma.rn.f32x2 %0, %1, %2, %0;" : "+l"(d) : "l"(a), "l"(b));
}
__device__ __forceinline__ u64 mul2(u64 a, u64 b) {
    u64 d; asm("mul.rn.f32x2 %0, %1, %2;" : "=l"(d) : "l"(a), "l"(b)); return d;
}
__device__ __forceinline__ float fex2(float x) {
    float r; asm("ex2.approx.f32 %0, %1;" : "=f"(r) : "f"(x)); return r;
}
__device__ __forceinline__ float frcp(float x) {
    float r; asm("rcp.approx.f32 %0, %1;" : "=f"(r) : "f"(x)); return r;
}

__global__ __launch_bounds__(256, 1)
void reservoir_kernel(const float* __restrict__ rain,
                      const float* __restrict__ w_in,
                      const float* __restrict__ w,
                      float* __restrict__ out)
{
    const int tid = blockIdx.x * 256 + threadIdx.x;
    const int b   = tid >> 2;        // chain
    const int h   = tid & 3;         // lane within chain, owns rows 4h..4h+3
    const float C = 2.8853900817779268f;  // 2*log2(e)

    // Wp[r][m] = ( -2C*W[4h+r][c0], -2C*W[4h+r][c0+1] ),  c0 = (4h)^(2m)
    u64  Wp[4][8];
    float cwin[4], cs[4];
#pragma unroll
    for (int r = 0; r < 4; ++r) {
        const int row = 4 * h + r;
        float s = 0.f;
#pragma unroll
        for (int c = 0; c < HID; ++c) s += w[row * HID + c];
        cs[r]   = C * s;
        cwin[r] = C * w_in[row];
#pragma unroll
        for (int m = 0; m < 8; ++m) {
            const int c0 = (4 * h) ^ (2 * m);
            Wp[r][m] = pack2(-2.f * C * w[row * HID + c0],
                             -2.f * C * w[row * HID + c0 + 1]);
        }
    }

    // state pairs: xp[m] = ( r[(4h)^(2m)], r[(4h)^(2m)+1] ); x=0 -> r=0.5
    u64 xp[8];
#pragma unroll
    for (int m = 0; m < 8; ++m) xp[m] = pack2(0.5f, 0.5f);

    const float4* up = reinterpret_cast<const float4*>(rain + (size_t)b * TT);
    float4 ua = up[0], ub = up[1];

    float rr0, rr1, rr2, rr3;
    const int NG = TT / 8;

#define STEP(UVAL)                                                            \
    do {                                                                      \
        u64 A0 = mul2(Wp[0][0], xp[0]);                                       \
        u64 A1 = mul2(Wp[1][0], xp[0]);                                       \
        u64 A2 = mul2(Wp[2][0], xp[0]);                                       \
        u64 A3 = mul2(Wp[3][0], xp[0]);                                       \
        _Pragma("unroll")                                                     \
        for (int m = 1; m < 8; ++m) {                                         \
            fma2(A0, Wp[0][m], xp[m]);                                        \
            fma2(A1, Wp[1][m], xp[m]);                                        \
            fma2(A2, Wp[2][m], xp[m]);                                        \
            fma2(A3, Wp[3][m], xp[m]);                                        \
        }                                                                     \
        {                                                                     \
            float lo, hi, pre;                                                \
            unpack2(A0, lo, hi);                                              \
            pre = (lo + hi) + fmaf(cwin[0], (UVAL), cs[0]);                   \
            rr0 = frcp(fex2(pre) + 1.f);                                      \
            unpack2(A1, lo, hi);                                              \
            pre = (lo + hi) + fmaf(cwin[1], (UVAL), cs[1]);                   \
            rr1 = frcp(fex2(pre) + 1.f);                                      \
            unpack2(A2, lo, hi);                                              \
            pre = (lo + hi) + fmaf(cwin[2], (UVAL), cs[2]);                   \
            rr2 = frcp(fex2(pre) + 1.f);                                      \
            unpack2(A3, lo, hi);                                              \
            pre = (lo + hi) + fmaf(cwin[3], (UVAL), cs[3]);                   \
            rr3 = frcp(fex2(pre) + 1.f);                                      \
        }                                                                     \
        float o0 = __shfl_xor_sync(0xFFFFFFFFu, rr0, 1);                      \
        float o1 = __shfl_xor_sync(0xFFFFFFFFu, rr1, 1);                      \
        float o2 = __shfl_xor_sync(0xFFFFFFFFu, rr2, 1);                      \
        float o3 = __shfl_xor_sync(0xFFFFFFFFu, rr3, 1);                      \
        float p0 = __shfl_xor_sync(0xFFFFFFFFu, rr0, 2);                      \
        float p1 = __shfl_xor_sync(0xFFFFFFFFu, rr1, 2);                      \
        float p2 = __shfl_xor_sync(0xFFFFFFFFu, rr2, 2);                      \
        float p3 = __shfl_xor_sync(0xFFFFFFFFu, rr3, 2);                      \
        float q0 = __shfl_xor_sync(0xFFFFFFFFu, o0, 2);                       \
        float q1 = __shfl_xor_sync(0xFFFFFFFFu, o1, 2);                       \
        float q2 = __shfl_xor_sync(0xFFFFFFFFu, o2, 2);                       \
        float q3 = __shfl_xor_sync(0xFFFFFFFFu, o3, 2);                       \
        xp[0] = pack2(rr0, rr1); xp[1] = pack2(rr2, rr3);                     \
        xp[2] = pack2(o0, o1);   xp[3] = pack2(o2, o3);                       \
        xp[4] = pack2(p0, p1);   xp[5] = pack2(p2, p3);                       \
        xp[6] = pack2(q0, q1);   xp[7] = pack2(q2, q3);                       \
    } while (0)

    for (int g = 0; g < NG; ++g) {
        const int pg = (g + 1 < NG) ? (g + 1) : g;   // clamp; last iter reloads
        const float4 na = up[2 * pg];
        const float4 nb = up[2 * pg + 1];

        STEP(ua.x); STEP(ua.y); STEP(ua.z); STEP(ua.w);
        STEP(ub.x); STEP(ub.y); STEP(ub.z); STEP(ub.w);

        ua = na; ub = nb;
    }
#undef STEP

    // final: t = 1 - 2r for own 4 rows
    float* ob = out + (size_t)b * HID + 4 * h;
    reinterpret_cast<float4*>(ob)[0] =
        make_float4(fmaf(-2.f, rr0, 1.f), fmaf(-2.f, rr1, 1.f),
                    fmaf(-2.f, rr2, 1.f), fmaf(-2.f, rr3, 1.f));
}

extern "C" void kernel_launch(void* const* d_in, const int* in_sizes, int n_in,
                              void* d_out, int out_size)
{
    const float* rain = (const float*)d_in[0];   // (B, T, 1) f32
    const float* w_in = (const float*)d_in[1];   // (16, 1)   f32
    const float* w    = (const float*)d_in[2];   // (16, 16)  f32
    float* out        = (float*)d_out;           // (B, 16)   f32

    reservoir_kernel<<<(BB * 4) / 256, 256>>>(rain, w_in, w, out);
}